// round 2
// baseline (speedup 1.0000x reference)
#include <cuda_runtime.h>
#include <mma.h>

using namespace nvcuda;

// ---------------- Problem constants ----------------
#define T_TOK   2048
#define HID     4096
#define NQ      32
#define NKV     8
#define HD      128
#define QKV_N   6144            // (32 + 2*8) * 128
#define O_N     4096            // NQ * HD

// Scratch (allocation-free rule: __device__ globals)
__device__ float g_qkv[(size_t)T_TOK * QKV_N];   // qkv = hidden @ w_qkv (then normed/roped in place)
__device__ float g_attn[(size_t)T_TOK * O_N];    // attention output before o-proj

// ---------------- cp.async helpers ----------------
__device__ __forceinline__ void cp_async16(void* smem_dst, const void* gmem_src) {
    unsigned s = (unsigned)__cvta_generic_to_shared(smem_dst);
    asm volatile("cp.async.cg.shared.global [%0], [%1], 16;\n" :: "r"(s), "l"(gmem_src));
}
__device__ __forceinline__ void cp_commit() {
    asm volatile("cp.async.commit_group;\n");
}
template <int N>
__device__ __forceinline__ void cp_wait() {
    asm volatile("cp.async.wait_group %0;\n" :: "n"(N));
}

// ======================================================================
// TF32 wmma GEMM: C[M,N] = A[M,K] @ B[K,N], all row-major fp32.
// Block tile 128x128x32, 256 threads (8 warps), warp tile 64x32.
// Double-buffered smem, cp.async pipeline (load k+1 overlaps compute k).
// ======================================================================
#define BM 128
#define BN 128
#define BK 32
#define SA_LD 40     // 32 + 8 pad
#define SB_LD 136    // 128 + 8 pad
#define SA_BUF (BM * SA_LD)          // 5120 floats
#define SB_BUF (BK * SB_LD)          // 4352 floats
#define GEMM_SMEM_BYTES ((2 * SA_BUF + 2 * SB_BUF) * 4)   // 75776 B

__global__ __launch_bounds__(256) void gemm_tf32(const float* __restrict__ A,
                                                 const float* __restrict__ B,
                                                 float* __restrict__ C,
                                                 int M, int N, int K)
{
    extern __shared__ float smem[];
    float* sA = smem;                     // 2 buffers
    float* sB = smem + 2 * SA_BUF;        // 2 buffers

    const int tid  = threadIdx.x;
    const int warp = tid >> 5;
    const int wm   = warp >> 2;       // 0..1
    const int wn   = warp & 3;        // 0..3
    const int m0   = blockIdx.y * BM;
    const int n0   = blockIdx.x * BN;

    const int ra[4] = { (tid + 0) >> 3, (tid + 256) >> 3, (tid + 512) >> 3, (tid + 768) >> 3 };
    const int ca    = (tid & 7) << 2;
    const int rb[4] = { (tid + 0) >> 5, (tid + 256) >> 5, (tid + 512) >> 5, (tid + 768) >> 5 };
    const int cb    = (tid & 31) << 2;

    wmma::fragment<wmma::accumulator, 16, 16, 8, float> acc[4][2];
#pragma unroll
    for (int i = 0; i < 4; i++)
#pragma unroll
        for (int j = 0; j < 2; j++)
            wmma::fill_fragment(acc[i][j], 0.0f);

    const int NT = K / BK;

    auto load_tile = [&](int kt, int buf) {
        const int kb = kt * BK;
        float* dA = sA + buf * SA_BUF;
        float* dB = sB + buf * SB_BUF;
#pragma unroll
        for (int i = 0; i < 4; i++)
            cp_async16(dA + ra[i] * SA_LD + ca, A + (size_t)(m0 + ra[i]) * K + kb + ca);
#pragma unroll
        for (int i = 0; i < 4; i++)
            cp_async16(dB + rb[i] * SB_LD + cb, B + (size_t)(kb + rb[i]) * N + n0 + cb);
    };

    load_tile(0, 0);
    cp_commit();

    for (int kt = 0; kt < NT; kt++) {
        const int buf = kt & 1;
        if (kt + 1 < NT) {
            load_tile(kt + 1, (kt + 1) & 1);
            cp_commit();
            cp_wait<1>();
        } else {
            cp_wait<0>();
        }
        __syncthreads();

        const float* tA = sA + buf * SA_BUF;
        const float* tB = sB + buf * SB_BUF;
#pragma unroll
        for (int kk = 0; kk < BK; kk += 8) {
            wmma::fragment<wmma::matrix_a, 16, 16, 8, wmma::precision::tf32, wmma::row_major> af[4];
            wmma::fragment<wmma::matrix_b, 16, 16, 8, wmma::precision::tf32, wmma::row_major> bf[2];
#pragma unroll
            for (int i = 0; i < 4; i++) {
                wmma::load_matrix_sync(af[i], tA + (wm * 64 + i * 16) * SA_LD + kk, SA_LD);
#pragma unroll
                for (int t = 0; t < af[i].num_elements; t++)
                    af[i].x[t] = wmma::__float_to_tf32(af[i].x[t]);
            }
#pragma unroll
            for (int j = 0; j < 2; j++) {
                wmma::load_matrix_sync(bf[j], tB + kk * SB_LD + wn * 32 + j * 16, SB_LD);
#pragma unroll
                for (int t = 0; t < bf[j].num_elements; t++)
                    bf[j].x[t] = wmma::__float_to_tf32(bf[j].x[t]);
            }
#pragma unroll
            for (int i = 0; i < 4; i++)
#pragma unroll
                for (int j = 0; j < 2; j++)
                    wmma::mma_sync(acc[i][j], af[i], bf[j], acc[i][j]);
        }
        __syncthreads();
    }

#pragma unroll
    for (int i = 0; i < 4; i++)
#pragma unroll
        for (int j = 0; j < 2; j++) {
            float* cp = C + (size_t)(m0 + wm * 64 + i * 16) * N + n0 + wn * 32 + j * 16;
            wmma::store_matrix_sync(cp, acc[i][j], N, wmma::mem_row_major);
        }
}

// ======================================================================
// Fused RMSNorm + RoPE, one warp per (token, head). q heads then k heads.
// ======================================================================
__global__ __launch_bounds__(128) void normrope_kernel(float* __restrict__ qkv,
                                                       const int* __restrict__ positions,
                                                       const float* __restrict__ qw,
                                                       const float* __restrict__ kw)
{
    const int gw   = blockIdx.x * 4 + (threadIdx.x >> 5);
    const int lane = threadIdx.x & 31;
    const int total = T_TOK * (NQ + NKV);
    if (gw >= total) return;
    const int t  = gw / (NQ + NKV);
    const int hh = gw - t * (NQ + NKV);
    const bool isq = (hh < NQ);
    const int base = isq ? hh * HD : NQ * HD + (hh - NQ) * HD;
    const float* w = isq ? qw : kw;

    float* x = qkv + (size_t)t * QKV_N + base;
    float x0 = x[lane];
    float x1 = x[lane + 32];
    float x2 = x[lane + 64];
    float x3 = x[lane + 96];

    float ss = x0 * x0 + x1 * x1 + x2 * x2 + x3 * x3;
#pragma unroll
    for (int o = 16; o; o >>= 1) ss += __shfl_xor_sync(0xffffffffu, ss, o);
    const float rinv = rsqrtf(ss * (1.0f / 128.0f) + 1e-6f);

    x0 *= rinv * w[lane];
    x1 *= rinv * w[lane + 32];
    x2 *= rinv * w[lane + 64];
    x3 *= rinv * w[lane + 96];

    const double p  = (double)positions[t];
    const double cc = 0.21586735246819178;   // ln(1e6) / 64
    double s0d, c0d, s1d, c1d;
    sincos(p * exp(-(double)lane * cc), &s0d, &c0d);
    sincos(p * exp(-(double)(lane + 32) * cc), &s1d, &c1d);
    const float c0 = (float)c0d, s0 = (float)s0d;
    const float c1 = (float)c1d, s1 = (float)s1d;

    x[lane]      = x0 * c0 - x2 * s0;
    x[lane + 64] = x2 * c0 + x0 * s0;
    x[lane + 32] = x1 * c1 - x3 * s1;
    x[lane + 96] = x3 * c1 + x1 * s1;
}

// ======================================================================
// Flash attention: block = (query tile of 64, head). 256 threads.
// ======================================================================
#define AQ_LD 136
#define AS_LD 72
#define ATTN_SMEM_FLOATS (8704 * 4 + 64 * AS_LD + 128)
#define ATTN_SMEM_BYTES  (ATTN_SMEM_FLOATS * 4)

__global__ __launch_bounds__(256) void attn_kernel(const float* __restrict__ qkv,
                                                   float* __restrict__ aout)
{
    extern __shared__ float sm[];
    float* sQ = sm;                 // 8704
    float* sK = sm + 8704;          // 8704
    float* sV = sm + 17408;         // 8704
    float* sS = sm + 26112;         // 4608
    float* sO = sm + 30720;         // 8704
    float* sM = sm + 39424;         // 64
    float* sL = sm + 39488;         // 64

    const int tid  = threadIdx.x;
    const int lane = tid & 31;
    const int warp = tid >> 5;
    const int qt   = blockIdx.x;
    const int h    = blockIdx.y;
    const int kvh  = h >> 2;
    const int q0   = qt * 64;
    const float scaling = 0.08838834764831845f;   // 128^-0.5

#pragma unroll
    for (int i = 0; i < 8; i++) {
        int e = tid + i * 256;
        int r = e >> 5;
        int c = (e & 31) << 2;
        float4 v = *(const float4*)(qkv + (size_t)(q0 + r) * QKV_N + h * HD + c);
        v.x *= scaling; v.y *= scaling; v.z *= scaling; v.w *= scaling;
        *(float4*)(sQ + r * AQ_LD + c) = v;
    }
    for (int i = tid; i < 8704; i += 256) sO[i] = 0.0f;
    if (tid < 64) { sM[tid] = -1e30f; sL[tid] = 0.0f; }
    __syncthreads();

    for (int kt = 0; kt <= qt; kt++) {
        const int k0 = kt * 64;
#pragma unroll
        for (int i = 0; i < 8; i++) {
            int e = tid + i * 256;
            int r = e >> 5;
            int c = (e & 31) << 2;
            const float* src = qkv + (size_t)(k0 + r) * QKV_N + NQ * HD + kvh * HD + c;
            *(float4*)(sK + r * AQ_LD + c) = *(const float4*)src;
            *(float4*)(sV + r * AQ_LD + c) = *(const float4*)(src + NKV * HD);
        }
        __syncthreads();

        // ---- S = Q K^T ----
        {
            const int tm  = warp >> 1;
            const int tn0 = (warp & 1) * 2;
#pragma unroll
            for (int jj = 0; jj < 2; jj++) {
                const int tn = tn0 + jj;
                wmma::fragment<wmma::accumulator, 16, 16, 8, float> c;
                wmma::fill_fragment(c, 0.0f);
#pragma unroll
                for (int d = 0; d < HD; d += 8) {
                    wmma::fragment<wmma::matrix_a, 16, 16, 8, wmma::precision::tf32, wmma::row_major> a;
                    wmma::fragment<wmma::matrix_b, 16, 16, 8, wmma::precision::tf32, wmma::col_major> b;
                    wmma::load_matrix_sync(a, sQ + tm * 16 * AQ_LD + d, AQ_LD);
                    wmma::load_matrix_sync(b, sK + tn * 16 * AQ_LD + d, AQ_LD);
#pragma unroll
                    for (int t = 0; t < a.num_elements; t++) a.x[t] = wmma::__float_to_tf32(a.x[t]);
#pragma unroll
                    for (int t = 0; t < b.num_elements; t++) b.x[t] = wmma::__float_to_tf32(b.x[t]);
                    wmma::mma_sync(c, a, b, c);
                }
                wmma::store_matrix_sync(sS + tm * 16 * AS_LD + tn * 16, c, AS_LD, wmma::mem_row_major);
            }
        }
        __syncthreads();

        // ---- Online softmax ----
        const bool diag = (kt == qt);
#pragma unroll
        for (int rr = 0; rr < 8; rr++) {
            const int r    = warp * 8 + rr;
            const int qrow = q0 + r;
            float v0 = sS[r * AS_LD + lane];
            float v1 = sS[r * AS_LD + lane + 32];
            if (diag) {
                if (k0 + lane      > qrow) v0 = -1e30f;
                if (k0 + lane + 32 > qrow) v1 = -1e30f;
            }
            float mx = fmaxf(v0, v1);
#pragma unroll
            for (int o = 16; o; o >>= 1) mx = fmaxf(mx, __shfl_xor_sync(0xffffffffu, mx, o));
            const float mo = sM[r];
            const float mn = fmaxf(mo, mx);
            const float p0 = __expf(v0 - mn);
            const float p1 = __expf(v1 - mn);
            float s = p0 + p1;
#pragma unroll
            for (int o = 16; o; o >>= 1) s += __shfl_xor_sync(0xffffffffu, s, o);
            const float alpha = __expf(mo - mn);
            if (lane == 0) { sM[r] = mn; sL[r] = sL[r] * alpha + s; }
            sS[r * AS_LD + lane]      = p0;
            sS[r * AS_LD + lane + 32] = p1;
            sO[r * AQ_LD + lane]      *= alpha;
            sO[r * AQ_LD + lane + 32] *= alpha;
            sO[r * AQ_LD + lane + 64] *= alpha;
            sO[r * AQ_LD + lane + 96] *= alpha;
        }
        __syncthreads();

        // ---- O += P V ----
        {
            const int tm  = warp >> 1;
            const int tn0 = (warp & 1) * 4;
#pragma unroll
            for (int jj = 0; jj < 4; jj++) {
                const int tn = tn0 + jj;
                wmma::fragment<wmma::accumulator, 16, 16, 8, float> c;
                wmma::load_matrix_sync(c, sO + tm * 16 * AQ_LD + tn * 16, AQ_LD, wmma::mem_row_major);
#pragma unroll
                for (int kk = 0; kk < 64; kk += 8) {
                    wmma::fragment<wmma::matrix_a, 16, 16, 8, wmma::precision::tf32, wmma::row_major> a;
                    wmma::fragment<wmma::matrix_b, 16, 16, 8, wmma::precision::tf32, wmma::row_major> b;
                    wmma::load_matrix_sync(a, sS + tm * 16 * AS_LD + kk, AS_LD);
                    wmma::load_matrix_sync(b, sV + kk * AQ_LD + tn * 16, AQ_LD);
#pragma unroll
                    for (int t = 0; t < a.num_elements; t++) a.x[t] = wmma::__float_to_tf32(a.x[t]);
#pragma unroll
                    for (int t = 0; t < b.num_elements; t++) b.x[t] = wmma::__float_to_tf32(b.x[t]);
                    wmma::mma_sync(c, a, b, c);
                }
                wmma::store_matrix_sync(sO + tm * 16 * AQ_LD + tn * 16, c, AQ_LD, wmma::mem_row_major);
            }
        }
        __syncthreads();
    }

#pragma unroll
    for (int rr = 0; rr < 8; rr++) {
        const int r = warp * 8 + rr;
        const float inv = 1.0f / sL[r];
        float* dst = aout + (size_t)(q0 + r) * O_N + h * HD;
        dst[lane]      = sO[r * AQ_LD + lane]      * inv;
        dst[lane + 32] = sO[r * AQ_LD + lane + 32] * inv;
        dst[lane + 64] = sO[r * AQ_LD + lane + 64] * inv;
        dst[lane + 96] = sO[r * AQ_LD + lane + 96] * inv;
    }
}

// ======================================================================
// Launch
// ======================================================================
extern "C" void kernel_launch(void* const* d_in, const int* in_sizes, int n_in,
                              void* d_out, int out_size)
{
    (void)in_sizes; (void)n_in; (void)out_size;
    const int*   positions = (const int*)  d_in[0];
    const float* hidden    = (const float*)d_in[1];
    const float* w_qkv     = (const float*)d_in[2];
    const float* qw        = (const float*)d_in[3];
    const float* kw        = (const float*)d_in[4];
    const float* w_o       = (const float*)d_in[5];
    float*       out       = (float*)d_out;

    float *qkv_ptr, *attn_ptr;
    cudaGetSymbolAddress((void**)&qkv_ptr, g_qkv);
    cudaGetSymbolAddress((void**)&attn_ptr, g_attn);

    cudaFuncSetAttribute(gemm_tf32, cudaFuncAttributeMaxDynamicSharedMemorySize, GEMM_SMEM_BYTES);
    cudaFuncSetAttribute(attn_kernel, cudaFuncAttributeMaxDynamicSharedMemorySize, ATTN_SMEM_BYTES);

    gemm_tf32<<<dim3(QKV_N / BN, T_TOK / BM), 256, GEMM_SMEM_BYTES>>>(hidden, w_qkv, qkv_ptr, T_TOK, QKV_N, HID);
    normrope_kernel<<<(T_TOK * (NQ + NKV)) / 4, 128>>>(qkv_ptr, positions, qw, kw);
    attn_kernel<<<dim3(T_TOK / 64, NQ), 256, ATTN_SMEM_BYTES>>>(qkv_ptr, attn_ptr);
    gemm_tf32<<<dim3(O_N / BN, T_TOK / BM), 256, GEMM_SMEM_BYTES>>>(attn_ptr, w_o, out, T_TOK, O_N, HID);
}

// round 3
// speedup vs baseline: 1.1595x; 1.1595x over previous
#include <cuda_runtime.h>
#include <mma.h>

using namespace nvcuda;

// ---------------- Problem constants ----------------
#define T_TOK   2048
#define HID     4096
#define NQ      32
#define NKV     8
#define HD      128
#define QKV_N   6144            // (32 + 2*8) * 128
#define O_N     4096            // NQ * HD

// Scratch (allocation-free rule: __device__ globals)
__device__ float g_qkv [(size_t)T_TOK * QKV_N];   // qkv GEMM out, then normed/roped/rounded in place
__device__ float g_attn[(size_t)T_TOK * O_N];     // attention out (tf32-rounded at write)
__device__ float g_hid_r [(size_t)T_TOK * HID];   // hidden, tf32-rounded
__device__ float g_wqkv_r[(size_t)HID * QKV_N];   // w_qkv, tf32-rounded
__device__ float g_wo_r  [(size_t)HID * O_N];     // w_o, tf32-rounded  (HID == NQ*HD)

__device__ __forceinline__ float to_tf32(float x) {
    float r;
    asm("cvt.rna.tf32.f32 %0, %1;" : "=f"(r) : "f"(x));
    return r;
}

// ---------------- cp.async helpers ----------------
__device__ __forceinline__ void cp_async16(void* smem_dst, const void* gmem_src) {
    unsigned s = (unsigned)__cvta_generic_to_shared(smem_dst);
    asm volatile("cp.async.cg.shared.global [%0], [%1], 16;\n" :: "r"(s), "l"(gmem_src));
}
__device__ __forceinline__ void cp_commit() {
    asm volatile("cp.async.commit_group;\n");
}
template <int N>
__device__ __forceinline__ void cp_wait() {
    asm volatile("cp.async.wait_group %0;\n" :: "n"(N));
}

// ======================================================================
// Elementwise RNA-round to tf32 (float4 vectorized)
// ======================================================================
__global__ __launch_bounds__(256) void round_tf32_kernel(const float4* __restrict__ in,
                                                         float4* __restrict__ out, int n4)
{
    int i = blockIdx.x * 256 + threadIdx.x;
    if (i < n4) {
        float4 v = in[i];
        v.x = to_tf32(v.x); v.y = to_tf32(v.y);
        v.z = to_tf32(v.z); v.w = to_tf32(v.w);
        out[i] = v;
    }
}

// ======================================================================
// TF32 wmma GEMM: C[M,N] = A[M,K] @ B[K,N], row-major. Inputs ALREADY
// tf32-rounded -> no cvt in the mainloop.
// Block tile 128x128x32, 256 threads (8 warps), warp tile 64x32.
// Double-buffered smem, cp.async pipeline.
// ======================================================================
#define BM 128
#define BN 128
#define BK 32
#define SA_LD 40     // 32 + 8 pad
#define SB_LD 136    // 128 + 8 pad
#define SA_BUF (BM * SA_LD)          // 5120 floats
#define SB_BUF (BK * SB_LD)          // 4352 floats
#define GEMM_SMEM_BYTES ((2 * SA_BUF + 2 * SB_BUF) * 4)   // 75776 B

__global__ __launch_bounds__(256, 2) void gemm_tf32(const float* __restrict__ A,
                                                    const float* __restrict__ B,
                                                    float* __restrict__ C,
                                                    int M, int N, int K)
{
    extern __shared__ float smem[];
    float* sA = smem;                     // 2 buffers
    float* sB = smem + 2 * SA_BUF;        // 2 buffers

    const int tid  = threadIdx.x;
    const int warp = tid >> 5;
    const int wm   = warp >> 2;       // 0..1
    const int wn   = warp & 3;        // 0..3
    const int m0   = blockIdx.y * BM;
    const int n0   = blockIdx.x * BN;

    const int ra[4] = { (tid + 0) >> 3, (tid + 256) >> 3, (tid + 512) >> 3, (tid + 768) >> 3 };
    const int ca    = (tid & 7) << 2;
    const int rb[4] = { (tid + 0) >> 5, (tid + 256) >> 5, (tid + 512) >> 5, (tid + 768) >> 5 };
    const int cb    = (tid & 31) << 2;

    wmma::fragment<wmma::accumulator, 16, 16, 8, float> acc[4][2];
#pragma unroll
    for (int i = 0; i < 4; i++)
#pragma unroll
        for (int j = 0; j < 2; j++)
            wmma::fill_fragment(acc[i][j], 0.0f);

    const int NT = K / BK;

    auto load_tile = [&](int kt, int buf) {
        const int kb = kt * BK;
        float* dA = sA + buf * SA_BUF;
        float* dB = sB + buf * SB_BUF;
#pragma unroll
        for (int i = 0; i < 4; i++)
            cp_async16(dA + ra[i] * SA_LD + ca, A + (size_t)(m0 + ra[i]) * K + kb + ca);
#pragma unroll
        for (int i = 0; i < 4; i++)
            cp_async16(dB + rb[i] * SB_LD + cb, B + (size_t)(kb + rb[i]) * N + n0 + cb);
    };

    load_tile(0, 0);
    cp_commit();

    for (int kt = 0; kt < NT; kt++) {
        const int buf = kt & 1;
        if (kt + 1 < NT) {
            load_tile(kt + 1, (kt + 1) & 1);
            cp_commit();
            cp_wait<1>();
        } else {
            cp_wait<0>();
        }
        __syncthreads();

        const float* tA = sA + buf * SA_BUF;
        const float* tB = sB + buf * SB_BUF;
#pragma unroll
        for (int kk = 0; kk < BK; kk += 8) {
            wmma::fragment<wmma::matrix_a, 16, 16, 8, wmma::precision::tf32, wmma::row_major> af[4];
            wmma::fragment<wmma::matrix_b, 16, 16, 8, wmma::precision::tf32, wmma::row_major> bf[2];
#pragma unroll
            for (int i = 0; i < 4; i++)
                wmma::load_matrix_sync(af[i], tA + (wm * 64 + i * 16) * SA_LD + kk, SA_LD);
#pragma unroll
            for (int j = 0; j < 2; j++)
                wmma::load_matrix_sync(bf[j], tB + kk * SB_LD + wn * 32 + j * 16, SB_LD);
#pragma unroll
            for (int i = 0; i < 4; i++)
#pragma unroll
                for (int j = 0; j < 2; j++)
                    wmma::mma_sync(acc[i][j], af[i], bf[j], acc[i][j]);
        }
        __syncthreads();
    }

#pragma unroll
    for (int i = 0; i < 4; i++)
#pragma unroll
        for (int j = 0; j < 2; j++) {
            float* cp = C + (size_t)(m0 + wm * 64 + i * 16) * N + n0 + wn * 32 + j * 16;
            wmma::store_matrix_sync(cp, acc[i][j], N, wmma::mem_row_major);
        }
}

// ======================================================================
// Fused RMSNorm + RoPE + tf32 rounding. One warp per (token, head).
// 48 heads/token: 0-31 q (norm+rope), 32-39 k (norm+rope), 40-47 v (round only).
// RoPE angles computed in fp32 to match the reference bit-for-bit-ish.
// ======================================================================
__global__ __launch_bounds__(128) void normrope_kernel(float* __restrict__ qkv,
                                                       const int* __restrict__ positions,
                                                       const float* __restrict__ qw,
                                                       const float* __restrict__ kw)
{
    const int gw   = blockIdx.x * 4 + (threadIdx.x >> 5);
    const int lane = threadIdx.x & 31;
    const int total = T_TOK * 48;
    if (gw >= total) return;
    const int t  = gw / 48;
    const int hh = gw - t * 48;

    float* x = qkv + (size_t)t * QKV_N + hh * HD;
    float x0 = x[lane];
    float x1 = x[lane + 32];
    float x2 = x[lane + 64];
    float x3 = x[lane + 96];

    if (hh >= 40) {   // v head: just round to tf32
        x[lane]      = to_tf32(x0);
        x[lane + 32] = to_tf32(x1);
        x[lane + 64] = to_tf32(x2);
        x[lane + 96] = to_tf32(x3);
        return;
    }

    const float* w = (hh < NQ) ? qw : kw;

    float ss = x0 * x0 + x1 * x1 + x2 * x2 + x3 * x3;
#pragma unroll
    for (int o = 16; o; o >>= 1) ss += __shfl_xor_sync(0xffffffffu, ss, o);
    const float rinv = rsqrtf(ss * (1.0f / 128.0f) + 1e-6f);

    x0 *= rinv * w[lane];
    x1 *= rinv * w[lane + 32];
    x2 *= rinv * w[lane + 64];
    x3 *= rinv * w[lane + 96];

    // RoPE: pair (d, d+64), inv_freq = theta^{-d/64}, all fp32 like the reference.
    const float p = (float)positions[t];
    const float inv0 = powf(1.0e6f, -((float)lane)        * (1.0f / 64.0f));
    const float inv1 = powf(1.0e6f, -((float)(lane + 32)) * (1.0f / 64.0f));
    float s0, c0, s1, c1;
    sincosf(p * inv0, &s0, &c0);
    sincosf(p * inv1, &s1, &c1);

    x[lane]      = to_tf32(x0 * c0 - x2 * s0);
    x[lane + 64] = to_tf32(x2 * c0 + x0 * s0);
    x[lane + 32] = to_tf32(x1 * c1 - x3 * s1);
    x[lane + 96] = to_tf32(x3 * c1 + x1 * s1);
}

// ======================================================================
// Flash attention: block = (query tile of 64, head). 256 threads.
// Q/K/V are already tf32-rounded; only P fragments get cvt'd.
// Softmax applies the 128^-0.5 scale (Q is NOT pre-scaled).
// ======================================================================
#define AQ_LD 136
#define AS_LD 72
#define ATTN_SMEM_FLOATS (8704 * 4 + 64 * AS_LD + 128)
#define ATTN_SMEM_BYTES  (ATTN_SMEM_FLOATS * 4)

__global__ __launch_bounds__(256) void attn_kernel(const float* __restrict__ qkv,
                                                   float* __restrict__ aout)
{
    extern __shared__ float sm[];
    float* sQ = sm;                 // 8704
    float* sK = sm + 8704;          // 8704
    float* sV = sm + 17408;         // 8704
    float* sS = sm + 26112;         // 4608
    float* sO = sm + 30720;         // 8704
    float* sM = sm + 39424;         // 64
    float* sL = sm + 39488;         // 64

    const int tid  = threadIdx.x;
    const int lane = tid & 31;
    const int warp = tid >> 5;
    const int qt   = blockIdx.x;
    const int h    = blockIdx.y;
    const int kvh  = h >> 2;
    const int q0   = qt * 64;
    const float scaling = 0.08838834764831845f;   // 128^-0.5

#pragma unroll
    for (int i = 0; i < 8; i++) {
        int e = tid + i * 256;
        int r = e >> 5;
        int c = (e & 31) << 2;
        *(float4*)(sQ + r * AQ_LD + c) =
            *(const float4*)(qkv + (size_t)(q0 + r) * QKV_N + h * HD + c);
    }
    for (int i = tid; i < 8704; i += 256) sO[i] = 0.0f;
    if (tid < 64) { sM[tid] = -1e30f; sL[tid] = 0.0f; }
    __syncthreads();

    for (int kt = 0; kt <= qt; kt++) {
        const int k0 = kt * 64;
#pragma unroll
        for (int i = 0; i < 8; i++) {
            int e = tid + i * 256;
            int r = e >> 5;
            int c = (e & 31) << 2;
            const float* src = qkv + (size_t)(k0 + r) * QKV_N + NQ * HD + kvh * HD + c;
            *(float4*)(sK + r * AQ_LD + c) = *(const float4*)src;
            *(float4*)(sV + r * AQ_LD + c) = *(const float4*)(src + NKV * HD);
        }
        __syncthreads();

        // ---- S = Q K^T (Q,K pre-rounded -> no cvt) ----
        {
            const int tm  = warp >> 1;
            const int tn0 = (warp & 1) * 2;
#pragma unroll
            for (int jj = 0; jj < 2; jj++) {
                const int tn = tn0 + jj;
                wmma::fragment<wmma::accumulator, 16, 16, 8, float> c;
                wmma::fill_fragment(c, 0.0f);
#pragma unroll
                for (int d = 0; d < HD; d += 8) {
                    wmma::fragment<wmma::matrix_a, 16, 16, 8, wmma::precision::tf32, wmma::row_major> a;
                    wmma::fragment<wmma::matrix_b, 16, 16, 8, wmma::precision::tf32, wmma::col_major> b;
                    wmma::load_matrix_sync(a, sQ + tm * 16 * AQ_LD + d, AQ_LD);
                    wmma::load_matrix_sync(b, sK + tn * 16 * AQ_LD + d, AQ_LD);
                    wmma::mma_sync(c, a, b, c);
                }
                wmma::store_matrix_sync(sS + tm * 16 * AS_LD + tn * 16, c, AS_LD, wmma::mem_row_major);
            }
        }
        __syncthreads();

        // ---- Online softmax (scale applied here) ----
        const bool diag = (kt == qt);
#pragma unroll
        for (int rr = 0; rr < 8; rr++) {
            const int r    = warp * 8 + rr;
            const int qrow = q0 + r;
            float v0 = sS[r * AS_LD + lane]      * scaling;
            float v1 = sS[r * AS_LD + lane + 32] * scaling;
            if (diag) {
                if (k0 + lane      > qrow) v0 = -1e30f;
                if (k0 + lane + 32 > qrow) v1 = -1e30f;
            }
            float mx = fmaxf(v0, v1);
#pragma unroll
            for (int o = 16; o; o >>= 1) mx = fmaxf(mx, __shfl_xor_sync(0xffffffffu, mx, o));
            const float mo = sM[r];
            const float mn = fmaxf(mo, mx);
            const float p0 = __expf(v0 - mn);
            const float p1 = __expf(v1 - mn);
            float s = p0 + p1;
#pragma unroll
            for (int o = 16; o; o >>= 1) s += __shfl_xor_sync(0xffffffffu, s, o);
            const float alpha = __expf(mo - mn);
            if (lane == 0) { sM[r] = mn; sL[r] = sL[r] * alpha + s; }
            sS[r * AS_LD + lane]      = p0;
            sS[r * AS_LD + lane + 32] = p1;
            sO[r * AQ_LD + lane]      *= alpha;
            sO[r * AQ_LD + lane + 32] *= alpha;
            sO[r * AQ_LD + lane + 64] *= alpha;
            sO[r * AQ_LD + lane + 96] *= alpha;
        }
        __syncthreads();

        // ---- O += P V (V pre-rounded; cvt only on P) ----
        {
            const int tm  = warp >> 1;
            const int tn0 = (warp & 1) * 4;
#pragma unroll
            for (int jj = 0; jj < 4; jj++) {
                const int tn = tn0 + jj;
                wmma::fragment<wmma::accumulator, 16, 16, 8, float> c;
                wmma::load_matrix_sync(c, sO + tm * 16 * AQ_LD + tn * 16, AQ_LD, wmma::mem_row_major);
#pragma unroll
                for (int kk = 0; kk < 64; kk += 8) {
                    wmma::fragment<wmma::matrix_a, 16, 16, 8, wmma::precision::tf32, wmma::row_major> a;
                    wmma::fragment<wmma::matrix_b, 16, 16, 8, wmma::precision::tf32, wmma::row_major> b;
                    wmma::load_matrix_sync(a, sS + tm * 16 * AS_LD + kk, AS_LD);
                    wmma::load_matrix_sync(b, sV + kk * AQ_LD + tn * 16, AQ_LD);
#pragma unroll
                    for (int t = 0; t < a.num_elements; t++) a.x[t] = to_tf32(a.x[t]);
                    wmma::mma_sync(c, a, b, c);
                }
                wmma::store_matrix_sync(sO + tm * 16 * AQ_LD + tn * 16, c, AQ_LD, wmma::mem_row_major);
            }
        }
        __syncthreads();
    }

    // ---- Epilogue: normalize, round to tf32 (feeds O-proj GEMM directly) ----
#pragma unroll
    for (int rr = 0; rr < 8; rr++) {
        const int r = warp * 8 + rr;
        const float inv = 1.0f / sL[r];
        float* dst = aout + (size_t)(q0 + r) * O_N + h * HD;
        dst[lane]      = to_tf32(sO[r * AQ_LD + lane]      * inv);
        dst[lane + 32] = to_tf32(sO[r * AQ_LD + lane + 32] * inv);
        dst[lane + 64] = to_tf32(sO[r * AQ_LD + lane + 64] * inv);
        dst[lane + 96] = to_tf32(sO[r * AQ_LD + lane + 96] * inv);
    }
}

// ======================================================================
// Launch
// ======================================================================
extern "C" void kernel_launch(void* const* d_in, const int* in_sizes, int n_in,
                              void* d_out, int out_size)
{
    (void)in_sizes; (void)n_in; (void)out_size;
    const int*   positions = (const int*)  d_in[0];
    const float* hidden    = (const float*)d_in[1];
    const float* w_qkv     = (const float*)d_in[2];
    const float* qw        = (const float*)d_in[3];
    const float* kw        = (const float*)d_in[4];
    const float* w_o       = (const float*)d_in[5];
    float*       out       = (float*)d_out;

    float *qkv_ptr, *attn_ptr, *hid_r, *wqkv_r, *wo_r;
    cudaGetSymbolAddress((void**)&qkv_ptr, g_qkv);
    cudaGetSymbolAddress((void**)&attn_ptr, g_attn);
    cudaGetSymbolAddress((void**)&hid_r,  g_hid_r);
    cudaGetSymbolAddress((void**)&wqkv_r, g_wqkv_r);
    cudaGetSymbolAddress((void**)&wo_r,   g_wo_r);

    cudaFuncSetAttribute(gemm_tf32, cudaFuncAttributeMaxDynamicSharedMemorySize, GEMM_SMEM_BYTES);
    cudaFuncSetAttribute(attn_kernel, cudaFuncAttributeMaxDynamicSharedMemorySize, ATTN_SMEM_BYTES);

    // 0) pre-round GEMM operands to tf32 (RNA, once)
    {
        int n4;
        n4 = (T_TOK * HID) / 4;
        round_tf32_kernel<<<(n4 + 255) / 256, 256>>>((const float4*)hidden, (float4*)hid_r, n4);
        n4 = (HID * QKV_N) / 4;
        round_tf32_kernel<<<(n4 + 255) / 256, 256>>>((const float4*)w_qkv, (float4*)wqkv_r, n4);
        n4 = (HID * O_N) / 4;
        round_tf32_kernel<<<(n4 + 255) / 256, 256>>>((const float4*)w_o, (float4*)wo_r, n4);
    }

    // 1) qkv = hidden @ w_qkv
    gemm_tf32<<<dim3(QKV_N / BN, T_TOK / BM), 256, GEMM_SMEM_BYTES>>>(hid_r, wqkv_r, qkv_ptr, T_TOK, QKV_N, HID);
    // 2) rmsnorm + rope + tf32 rounding (q,k) and rounding (v), in place
    normrope_kernel<<<(T_TOK * 48) / 4, 128>>>(qkv_ptr, positions, qw, kw);
    // 3) causal flash attention (writes tf32-rounded attn out)
    attn_kernel<<<dim3(T_TOK / 64, NQ), 256, ATTN_SMEM_BYTES>>>(qkv_ptr, attn_ptr);
    // 4) out = attn @ w_o
    gemm_tf32<<<dim3(O_N / BN, T_TOK / BM), 256, GEMM_SMEM_BYTES>>>(attn_ptr, wo_r, out, T_TOK, O_N, HID);
}

// round 8
// speedup vs baseline: 1.5307x; 1.3202x over previous
#include <cuda_runtime.h>
#include <mma.h>

using namespace nvcuda;

// ---------------- Problem constants ----------------
#define T_TOK   2048
#define HID     4096
#define NQ      32
#define NKV     8
#define HD      128
#define QKV_N   6144            // (32 + 2*8) * 128
#define O_N     4096            // NQ * HD

// Scratch (allocation-free rule: __device__ globals)
__device__ float g_qkv [(size_t)T_TOK * QKV_N];
__device__ float g_attn[(size_t)T_TOK * O_N];
__device__ float g_hid_r [(size_t)T_TOK * HID];
__device__ float g_wqkv_r[(size_t)HID * QKV_N];
__device__ float g_wo_r  [(size_t)HID * O_N];

__device__ __forceinline__ float to_tf32(float x) {
    float r;
    asm("cvt.rna.tf32.f32 %0, %1;" : "=f"(r) : "f"(x));
    return r;
}

// ---------------- cp.async helpers ----------------
__device__ __forceinline__ void cp_async16(void* smem_dst, const void* gmem_src) {
    unsigned s = (unsigned)__cvta_generic_to_shared(smem_dst);
    asm volatile("cp.async.cg.shared.global [%0], [%1], 16;\n" :: "r"(s), "l"(gmem_src));
}
__device__ __forceinline__ void cp_commit() {
    asm volatile("cp.async.commit_group;\n");
}
template <int N>
__device__ __forceinline__ void cp_wait() {
    asm volatile("cp.async.wait_group %0;\n" :: "n"(N));
}

// ---------------- raw tf32 mma (m16n8k8), defined register layouts ----
// D/C: d0,d1 -> row lane/4,   cols 2*(lane%4), +1
//      d2,d3 -> row lane/4+8, cols 2*(lane%4), +1
// A:   a0 (r=l/4, k=l%4)  a1 (r=l/4+8, k=l%4)  a2 (r=l/4, k=l%4+4)  a3 (r+8, k+4)
// B:   b0 (k=l%4, n=l/4)  b1 (k=l%4+4, n=l/4)
__device__ __forceinline__ void mma_tf32_16x8x8(float& d0, float& d1, float& d2, float& d3,
                                                float a0, float a1, float a2, float a3,
                                                float b0, float b1)
{
    asm volatile(
        "mma.sync.aligned.m16n8k8.row.col.f32.tf32.tf32.f32 "
        "{%0,%1,%2,%3}, {%4,%5,%6,%7}, {%8,%9}, {%0,%1,%2,%3};\n"
        : "+f"(d0), "+f"(d1), "+f"(d2), "+f"(d3)
        : "r"(__float_as_uint(a0)), "r"(__float_as_uint(a1)),
          "r"(__float_as_uint(a2)), "r"(__float_as_uint(a3)),
          "r"(__float_as_uint(b0)), "r"(__float_as_uint(b1)));
}

// ======================================================================
// Elementwise RNA-round to tf32 (float4 vectorized)
// ======================================================================
__global__ __launch_bounds__(256) void round_tf32_kernel(const float4* __restrict__ in,
                                                         float4* __restrict__ out, int n4)
{
    int i = blockIdx.x * 256 + threadIdx.x;
    if (i < n4) {
        float4 v = in[i];
        v.x = to_tf32(v.x); v.y = to_tf32(v.y);
        v.z = to_tf32(v.z); v.w = to_tf32(v.w);
        out[i] = v;
    }
}

// ======================================================================
// TF32 wmma GEMM: C[M,N] = A[M,K] @ B[K,N], row-major, inputs pre-rounded.
// Block tile 128x128x32, 256 threads, warp tile 64x32.
// 3-stage cp.async pipeline.
// ======================================================================
#define BM 128
#define BN 128
#define BK 32
#define SA_LD 40
#define SB_LD 136
#define SA_BUF (BM * SA_LD)          // 5120 floats
#define SB_BUF (BK * SB_LD)          // 4352 floats
#define STAGES 3
#define GEMM_SMEM_BYTES (STAGES * (SA_BUF + SB_BUF) * 4)   // 113664 B

__global__ __launch_bounds__(256, 2) void gemm_tf32(const float* __restrict__ A,
                                                    const float* __restrict__ B,
                                                    float* __restrict__ C,
                                                    int M, int N, int K)
{
    extern __shared__ float smem[];
    float* sA = smem;
    float* sB = smem + STAGES * SA_BUF;

    const int tid  = threadIdx.x;
    const int warp = tid >> 5;
    const int wm   = warp >> 2;
    const int wn   = warp & 3;
    const int m0   = blockIdx.y * BM;
    const int n0   = blockIdx.x * BN;

    const int ra[4] = { (tid + 0) >> 3, (tid + 256) >> 3, (tid + 512) >> 3, (tid + 768) >> 3 };
    const int ca    = (tid & 7) << 2;
    const int rb[4] = { (tid + 0) >> 5, (tid + 256) >> 5, (tid + 512) >> 5, (tid + 768) >> 5 };
    const int cb    = (tid & 31) << 2;

    wmma::fragment<wmma::accumulator, 16, 16, 8, float> acc[4][2];
#pragma unroll
    for (int i = 0; i < 4; i++)
#pragma unroll
        for (int j = 0; j < 2; j++)
            wmma::fill_fragment(acc[i][j], 0.0f);

    const int NT = K / BK;

    auto load_tile = [&](int kt, int st) {
        const int kb = kt * BK;
        float* dA = sA + st * SA_BUF;
        float* dB = sB + st * SB_BUF;
#pragma unroll
        for (int i = 0; i < 4; i++)
            cp_async16(dA + ra[i] * SA_LD + ca, A + (size_t)(m0 + ra[i]) * K + kb + ca);
#pragma unroll
        for (int i = 0; i < 4; i++)
            cp_async16(dB + rb[i] * SB_LD + cb, B + (size_t)(kb + rb[i]) * N + n0 + cb);
    };

    load_tile(0, 0); cp_commit();
    load_tile(1, 1); cp_commit();

    for (int kt = 0; kt < NT; kt++) {
        const int st = kt % STAGES;
        if (kt + 2 < NT) {
            load_tile(kt + 2, (kt + 2) % STAGES);
            cp_commit();
            cp_wait<2>();
        } else if (kt + 1 < NT) {
            cp_wait<1>();
        } else {
            cp_wait<0>();
        }
        __syncthreads();

        const float* tA = sA + st * SA_BUF;
        const float* tB = sB + st * SB_BUF;
#pragma unroll
        for (int kk = 0; kk < BK; kk += 8) {
            wmma::fragment<wmma::matrix_a, 16, 16, 8, wmma::precision::tf32, wmma::row_major> af[4];
            wmma::fragment<wmma::matrix_b, 16, 16, 8, wmma::precision::tf32, wmma::row_major> bf[2];
#pragma unroll
            for (int i = 0; i < 4; i++)
                wmma::load_matrix_sync(af[i], tA + (wm * 64 + i * 16) * SA_LD + kk, SA_LD);
#pragma unroll
            for (int j = 0; j < 2; j++)
                wmma::load_matrix_sync(bf[j], tB + kk * SB_LD + wn * 32 + j * 16, SB_LD);
#pragma unroll
            for (int i = 0; i < 4; i++)
#pragma unroll
                for (int j = 0; j < 2; j++)
                    wmma::mma_sync(acc[i][j], af[i], bf[j], acc[i][j]);
        }
        __syncthreads();
    }

#pragma unroll
    for (int i = 0; i < 4; i++)
#pragma unroll
        for (int j = 0; j < 2; j++) {
            float* cp = C + (size_t)(m0 + wm * 64 + i * 16) * N + n0 + wn * 32 + j * 16;
            wmma::store_matrix_sync(cp, acc[i][j], N, wmma::mem_row_major);
        }
}

// ======================================================================
// Fused RMSNorm + RoPE + tf32 rounding. One warp per (token, head).
// heads 0-31 q, 32-39 k (norm+rope), 40-47 v (round only).
// ======================================================================
__global__ __launch_bounds__(128) void normrope_kernel(float* __restrict__ qkv,
                                                       const int* __restrict__ positions,
                                                       const float* __restrict__ qw,
                                                       const float* __restrict__ kw)
{
    const int gw   = blockIdx.x * 4 + (threadIdx.x >> 5);
    const int lane = threadIdx.x & 31;
    const int total = T_TOK * 48;
    if (gw >= total) return;
    const int t  = gw / 48;
    const int hh = gw - t * 48;

    float* x = qkv + (size_t)t * QKV_N + hh * HD;
    float x0 = x[lane];
    float x1 = x[lane + 32];
    float x2 = x[lane + 64];
    float x3 = x[lane + 96];

    if (hh >= 40) {   // v head: just round to tf32
        x[lane]      = to_tf32(x0);
        x[lane + 32] = to_tf32(x1);
        x[lane + 64] = to_tf32(x2);
        x[lane + 96] = to_tf32(x3);
        return;
    }

    const float* w = (hh < NQ) ? qw : kw;

    float ss = x0 * x0 + x1 * x1 + x2 * x2 + x3 * x3;
#pragma unroll
    for (int o = 16; o; o >>= 1) ss += __shfl_xor_sync(0xffffffffu, ss, o);
    const float rinv = rsqrtf(ss * (1.0f / 128.0f) + 1e-6f);

    x0 *= rinv * w[lane];
    x1 *= rinv * w[lane + 32];
    x2 *= rinv * w[lane + 64];
    x3 *= rinv * w[lane + 96];

    const float p = (float)positions[t];
    const float inv0 = powf(1.0e6f, -((float)lane)        * (1.0f / 64.0f));
    const float inv1 = powf(1.0e6f, -((float)(lane + 32)) * (1.0f / 64.0f));
    float s0, c0, s1, c1;
    sincosf(p * inv0, &s0, &c0);
    sincosf(p * inv1, &s1, &c1);

    x[lane]      = to_tf32(x0 * c0 - x2 * s0);
    x[lane + 64] = to_tf32(x2 * c0 + x0 * s0);
    x[lane + 32] = to_tf32(x1 * c1 - x3 * s1);
    x[lane + 96] = to_tf32(x3 * c1 + x1 * s1);
}

// ======================================================================
// Flash attention v2-style, raw mma.sync tf32, O accumulators in registers.
// CTA = (128 q-rows, 1 head), 256 threads (8 warps), warp = 16 q-rows.
// Key tile = 64. P staged in per-warp-private smem.
// ======================================================================
#define ATQ 128
#define ATK 64
#define QLD 132
#define KLD 132
#define VLD 136
#define PLD 68
#define OFF_Q 0
#define OFF_K (ATQ * QLD)                    // 16896
#define OFF_V (OFF_K + ATK * KLD)            // 25344
#define OFF_P (OFF_V + ATK * VLD)            // 34048
#define ATTN_SMEM_FLOATS (OFF_P + 8 * 16 * PLD)   // 42752
#define ATTN_SMEM_BYTES  (ATTN_SMEM_FLOATS * 4)   // 171008

__global__ __launch_bounds__(256, 1) void attn2_kernel(const float* __restrict__ qkv,
                                                       float* __restrict__ aout)
{
    extern __shared__ float sm[];
    const int tid  = threadIdx.x;
    const int lane = tid & 31;
    const int w    = tid >> 5;
    const int lq   = lane >> 2;       // 0..7  (row group)
    const int lk   = lane & 3;        // 0..3  (k/col group)

    const int qt  = gridDim.x - 1 - blockIdx.x;   // heavy CTAs first
    const int h   = blockIdx.y;
    const int kvh = h >> 2;
    const int q0  = qt * ATQ;
    const float scaling = 0.08838834764831845f;   // 128^-0.5

    float* sQ = sm + OFF_Q;
    float* sK = sm + OFF_K;
    float* sV = sm + OFF_V;
    float* sP = sm + OFF_P + w * (16 * PLD);      // per-warp private

    // ---- load Q tile (128x128) via cp.async ----
#pragma unroll
    for (int i = 0; i < 16; i++) {
        int e = tid + i * 256;
        int r = e >> 5;
        int c = (e & 31) << 2;
        cp_async16(sQ + r * QLD + c, qkv + (size_t)(q0 + r) * QKV_N + h * HD + c);
    }
    cp_commit();

    // O accumulators: 16 n-tiles of m16n8 (rows w*16+lq, w*16+lq+8)
    float o[16][4];
#pragma unroll
    for (int t = 0; t < 16; t++) { o[t][0] = o[t][1] = o[t][2] = o[t][3] = 0.0f; }
    float m0 = -1e30f, m1 = -1e30f, l0 = 0.0f, l1 = 0.0f;

    const int grow0 = q0 + w * 16 + lq;
    const int nkt = 2 * (qt + 1);

    for (int kt = 0; kt < nkt; kt++) {
        const int k0 = kt * ATK;
        // issue K then V (separate groups so S can start when K lands)
        const float* kbase = qkv + (size_t)k0 * QKV_N + NQ * HD + kvh * HD;
        const float* vbase = kbase + NKV * HD;
#pragma unroll
        for (int i = 0; i < 8; i++) {
            int e = tid + i * 256;
            int r = e >> 5;
            int c = (e & 31) << 2;
            cp_async16(sK + r * KLD + c, kbase + (size_t)r * QKV_N + c);
        }
        cp_commit();
#pragma unroll
        for (int i = 0; i < 8; i++) {
            int e = tid + i * 256;
            int r = e >> 5;
            int c = (e & 31) << 2;
            cp_async16(sV + r * VLD + c, vbase + (size_t)r * QKV_N + c);
        }
        cp_commit();

        cp_wait<1>();          // Q (first iter) + K ready
        __syncthreads();

        // ---- S = Q K^T : per warp 16x64, 8 n-tiles ----
        float s[8][4];
#pragma unroll
        for (int j = 0; j < 8; j++) { s[j][0] = s[j][1] = s[j][2] = s[j][3] = 0.0f; }

        {
            const float* qa = sQ + (w * 16 + lq) * QLD + lk;
            const float* kb = sK + lq * KLD + lk;
#pragma unroll
            for (int kk = 0; kk < 16; kk++) {
                const float a0 = qa[kk * 8];
                const float a1 = qa[8 * QLD + kk * 8];
                const float a2 = qa[kk * 8 + 4];
                const float a3 = qa[8 * QLD + kk * 8 + 4];
#pragma unroll
                for (int j = 0; j < 8; j++) {
                    const float b0 = kb[j * 8 * KLD + kk * 8];
                    const float b1 = kb[j * 8 * KLD + kk * 8 + 4];
                    mma_tf32_16x8x8(s[j][0], s[j][1], s[j][2], s[j][3],
                                    a0, a1, a2, a3, b0, b1);
                }
            }
        }

        // ---- scale + causal mask ----
        const bool needmask = (k0 + ATK - 1 > grow0);
#pragma unroll
        for (int j = 0; j < 8; j++) {
            s[j][0] *= scaling; s[j][1] *= scaling;
            s[j][2] *= scaling; s[j][3] *= scaling;
            if (needmask) {
                const int c0 = k0 + j * 8 + 2 * lk;
                if (c0     > grow0)     s[j][0] = -1e30f;
                if (c0 + 1 > grow0)     s[j][1] = -1e30f;
                if (c0     > grow0 + 8) s[j][2] = -1e30f;
                if (c0 + 1 > grow0 + 8) s[j][3] = -1e30f;
            }
        }

        // ---- online softmax in registers ----
        float rmax0 = -1e30f, rmax1 = -1e30f;
#pragma unroll
        for (int j = 0; j < 8; j++) {
            rmax0 = fmaxf(rmax0, fmaxf(s[j][0], s[j][1]));
            rmax1 = fmaxf(rmax1, fmaxf(s[j][2], s[j][3]));
        }
        rmax0 = fmaxf(rmax0, __shfl_xor_sync(0xffffffffu, rmax0, 1));
        rmax0 = fmaxf(rmax0, __shfl_xor_sync(0xffffffffu, rmax0, 2));
        rmax1 = fmaxf(rmax1, __shfl_xor_sync(0xffffffffu, rmax1, 1));
        rmax1 = fmaxf(rmax1, __shfl_xor_sync(0xffffffffu, rmax1, 2));

        const float mn0 = fmaxf(m0, rmax0);
        const float mn1 = fmaxf(m1, rmax1);
        const float alpha0 = __expf(m0 - mn0);
        const float alpha1 = __expf(m1 - mn1);
        m0 = mn0; m1 = mn1;

        float sum0 = 0.0f, sum1 = 0.0f;
#pragma unroll
        for (int j = 0; j < 8; j++) {
            const float p0 = __expf(s[j][0] - mn0);
            const float p1 = __expf(s[j][1] - mn0);
            const float p2 = __expf(s[j][2] - mn1);
            const float p3 = __expf(s[j][3] - mn1);
            sum0 += p0 + p1; sum1 += p2 + p3;
            float2* dst0 = (float2*)(sP + lq * PLD + j * 8 + 2 * lk);
            float2* dst1 = (float2*)(sP + (lq + 8) * PLD + j * 8 + 2 * lk);
            *dst0 = make_float2(p0, p1);
            *dst1 = make_float2(p2, p3);
        }
        sum0 += __shfl_xor_sync(0xffffffffu, sum0, 1);
        sum0 += __shfl_xor_sync(0xffffffffu, sum0, 2);
        sum1 += __shfl_xor_sync(0xffffffffu, sum1, 1);
        sum1 += __shfl_xor_sync(0xffffffffu, sum1, 2);
        l0 = l0 * alpha0 + sum0;
        l1 = l1 * alpha1 + sum1;

        // rescale O in registers
#pragma unroll
        for (int t = 0; t < 16; t++) {
            o[t][0] *= alpha0; o[t][1] *= alpha0;
            o[t][2] *= alpha1; o[t][3] *= alpha1;
        }

        cp_wait<0>();          // V ready
        __syncthreads();

        // ---- O += P V : per warp 16x128, 16 n-tiles, k=64 ----
        {
            const float* pa = sP + lq * PLD + lk;
            const float* vb = sV + lk * VLD + lq;
#pragma unroll
            for (int kk = 0; kk < 8; kk++) {
                const float a0 = pa[kk * 8];
                const float a1 = pa[8 * PLD + kk * 8];
                const float a2 = pa[kk * 8 + 4];
                const float a3 = pa[8 * PLD + kk * 8 + 4];
#pragma unroll
                for (int t = 0; t < 16; t++) {
                    const float b0 = vb[kk * 8 * VLD + t * 8];
                    const float b1 = vb[(kk * 8 + 4) * VLD + t * 8];
                    mma_tf32_16x8x8(o[t][0], o[t][1], o[t][2], o[t][3],
                                    a0, a1, a2, a3, b0, b1);
                }
            }
        }
        __syncthreads();       // all warps done with sK/sV before next-iter overwrite
    }

    // ---- epilogue: normalize, round to tf32, write ----
    const float inv0 = 1.0f / l0;
    const float inv1 = 1.0f / l1;
    const int row0 = q0 + w * 16 + lq;
#pragma unroll
    for (int t = 0; t < 16; t++) {
        const int c = t * 8 + 2 * lk;
        float2 v0 = make_float2(to_tf32(o[t][0] * inv0), to_tf32(o[t][1] * inv0));
        float2 v1 = make_float2(to_tf32(o[t][2] * inv1), to_tf32(o[t][3] * inv1));
        *(float2*)(aout + (size_t)row0 * O_N + h * HD + c)       = v0;
        *(float2*)(aout + (size_t)(row0 + 8) * O_N + h * HD + c) = v1;
    }
}

// ======================================================================
// Launch
// ======================================================================
extern "C" void kernel_launch(void* const* d_in, const int* in_sizes, int n_in,
                              void* d_out, int out_size)
{
    (void)in_sizes; (void)n_in; (void)out_size;
    const int*   positions = (const int*)  d_in[0];
    const float* hidden    = (const float*)d_in[1];
    const float* w_qkv     = (const float*)d_in[2];
    const float* qw        = (const float*)d_in[3];
    const float* kw        = (const float*)d_in[4];
    const float* w_o       = (const float*)d_in[5];
    float*       out       = (float*)d_out;

    float *qkv_ptr, *attn_ptr, *hid_r, *wqkv_r, *wo_r;
    cudaGetSymbolAddress((void**)&qkv_ptr, g_qkv);
    cudaGetSymbolAddress((void**)&attn_ptr, g_attn);
    cudaGetSymbolAddress((void**)&hid_r,  g_hid_r);
    cudaGetSymbolAddress((void**)&wqkv_r, g_wqkv_r);
    cudaGetSymbolAddress((void**)&wo_r,   g_wo_r);

    cudaFuncSetAttribute(gemm_tf32,  cudaFuncAttributeMaxDynamicSharedMemorySize, GEMM_SMEM_BYTES);
    cudaFuncSetAttribute(attn2_kernel, cudaFuncAttributeMaxDynamicSharedMemorySize, ATTN_SMEM_BYTES);

    // 0) pre-round GEMM operands to tf32 (RNA, once)
    {
        int n4;
        n4 = (T_TOK * HID) / 4;
        round_tf32_kernel<<<(n4 + 255) / 256, 256>>>((const float4*)hidden, (float4*)hid_r, n4);
        n4 = (HID * QKV_N) / 4;
        round_tf32_kernel<<<(n4 + 255) / 256, 256>>>((const float4*)w_qkv, (float4*)wqkv_r, n4);
        n4 = (HID * O_N) / 4;
        round_tf32_kernel<<<(n4 + 255) / 256, 256>>>((const float4*)w_o, (float4*)wo_r, n4);
    }

    // 1) qkv = hidden @ w_qkv
    gemm_tf32<<<dim3(QKV_N / BN, T_TOK / BM), 256, GEMM_SMEM_BYTES>>>(hid_r, wqkv_r, qkv_ptr, T_TOK, QKV_N, HID);
    // 2) rmsnorm + rope + tf32 rounding, in place
    normrope_kernel<<<(T_TOK * 48) / 4, 128>>>(qkv_ptr, positions, qw, kw);
    // 3) causal flash attention (register-resident O)
    attn2_kernel<<<dim3(T_TOK / ATQ, NQ), 256, ATTN_SMEM_BYTES>>>(qkv_ptr, attn_ptr);
    // 4) out = attn @ w_o
    gemm_tf32<<<dim3(O_N / BN, T_TOK / BM), 256, GEMM_SMEM_BYTES>>>(attn_ptr, wo_r, out, T_TOK, O_N, HID);
}

// round 11
// speedup vs baseline: 1.6051x; 1.0486x over previous
#include <cuda_runtime.h>
#include <mma.h>

using namespace nvcuda;

// ---------------- Problem constants ----------------
#define T_TOK   2048
#define HID     4096
#define NQ      32
#define NKV     8
#define HD      128
#define QKV_N   6144            // (32 + 2*8) * 128
#define O_N     4096            // NQ * HD

// Scratch (allocation-free rule: __device__ globals)
__device__ float g_qkv [(size_t)T_TOK * QKV_N];
__device__ float g_attn[(size_t)T_TOK * O_N];
__device__ float g_hid_r [(size_t)T_TOK * HID];
__device__ float g_wqkv_r[(size_t)HID * QKV_N];
__device__ float g_wo_r  [(size_t)HID * O_N];

__device__ __forceinline__ float to_tf32(float x) {
    float r;
    asm("cvt.rna.tf32.f32 %0, %1;" : "=f"(r) : "f"(x));
    return r;
}

// ---------------- cp.async helpers ----------------
__device__ __forceinline__ void cp_async16(void* smem_dst, const void* gmem_src) {
    unsigned s = (unsigned)__cvta_generic_to_shared(smem_dst);
    asm volatile("cp.async.cg.shared.global [%0], [%1], 16;\n" :: "r"(s), "l"(gmem_src));
}
__device__ __forceinline__ void cp_commit() {
    asm volatile("cp.async.commit_group;\n");
}
template <int N>
__device__ __forceinline__ void cp_wait() {
    asm volatile("cp.async.wait_group %0;\n" :: "n"(N));
}

// ---------------- raw tf32 mma (m16n8k8) for attention ----------------
__device__ __forceinline__ void mma_tf32_16x8x8(float& d0, float& d1, float& d2, float& d3,
                                                float a0, float a1, float a2, float a3,
                                                float b0, float b1)
{
    asm volatile(
        "mma.sync.aligned.m16n8k8.row.col.f32.tf32.tf32.f32 "
        "{%0,%1,%2,%3}, {%4,%5,%6,%7}, {%8,%9}, {%0,%1,%2,%3};\n"
        : "+f"(d0), "+f"(d1), "+f"(d2), "+f"(d3)
        : "r"(__float_as_uint(a0)), "r"(__float_as_uint(a1)),
          "r"(__float_as_uint(a2)), "r"(__float_as_uint(a3)),
          "r"(__float_as_uint(b0)), "r"(__float_as_uint(b1)));
}

// ======================================================================
// Elementwise RNA-round to tf32 (float4 vectorized)
// ======================================================================
__global__ __launch_bounds__(256) void round_tf32_kernel(const float4* __restrict__ in,
                                                         float4* __restrict__ out, int n4)
{
    int i = blockIdx.x * 256 + threadIdx.x;
    if (i < n4) {
        float4 v = in[i];
        v.x = to_tf32(v.x); v.y = to_tf32(v.y);
        v.z = to_tf32(v.z); v.w = to_tf32(v.w);
        out[i] = v;
    }
}

// ======================================================================
// TF32 wmma GEMM: C[M,N] = A[M,K] @ B[K,N], row-major, inputs pre-rounded.
// Block tile 256x128x32, 256 threads (8 warps), warp tile 64x64.
// 2-stage cp.async double buffer. 1 CTA/SM (reg-bound), big-ILP mainloop:
// per kk step each warp does 8 fragment loads + 16 wmma (vs 6 loads / 8 wmma
// before) -> 3x fewer LDS issues per MMA and 16 independent acc chains.
// ======================================================================
#define BM 256
#define BN 128
#define BK 32
#define SA_LD 40     // 32 + 8 pad
#define SB_LD 136    // 128 + 8 pad
#define SA_BUF (BM * SA_LD)          // 10240 floats
#define SB_BUF (BK * SB_LD)          // 4352 floats
#define GEMM_SMEM_BYTES (2 * (SA_BUF + SB_BUF) * 4)   // 116736 B

__global__ __launch_bounds__(256) void gemm_tf32(const float* __restrict__ A,
                                                 const float* __restrict__ B,
                                                 float* __restrict__ C,
                                                 int M, int N, int K)
{
    extern __shared__ float smem[];
    float* sA = smem;                     // 2 buffers
    float* sB = smem + 2 * SA_BUF;        // 2 buffers

    const int tid  = threadIdx.x;
    const int warp = tid >> 5;
    const int wm   = warp >> 1;       // 0..3  (64-row band)
    const int wn   = warp & 1;        // 0..1  (64-col band)
    const int m0   = blockIdx.y * BM;
    const int n0   = blockIdx.x * BN;

    // A tile 256x32 = 2048 float4 -> 8 per thread; B tile 32x128 = 1024 -> 4
    const int ca = (tid & 7) << 2;
    const int cb = (tid & 31) << 2;

    wmma::fragment<wmma::accumulator, 16, 16, 8, float> acc[4][4];
#pragma unroll
    for (int i = 0; i < 4; i++)
#pragma unroll
        for (int j = 0; j < 4; j++)
            wmma::fill_fragment(acc[i][j], 0.0f);

    const int NT = K / BK;

    auto load_tile = [&](int kt, int buf) {
        const int kb = kt * BK;
        float* dA = sA + buf * SA_BUF;
        float* dB = sB + buf * SB_BUF;
#pragma unroll
        for (int i = 0; i < 8; i++) {
            int r = (tid + i * 256) >> 3;
            cp_async16(dA + r * SA_LD + ca, A + (size_t)(m0 + r) * K + kb + ca);
        }
#pragma unroll
        for (int i = 0; i < 4; i++) {
            int r = (tid + i * 256) >> 5;
            cp_async16(dB + r * SB_LD + cb, B + (size_t)(kb + r) * N + n0 + cb);
        }
    };

    load_tile(0, 0);
    cp_commit();

    for (int kt = 0; kt < NT; kt++) {
        const int buf = kt & 1;
        if (kt + 1 < NT) {
            load_tile(kt + 1, (kt + 1) & 1);
            cp_commit();
            cp_wait<1>();
        } else {
            cp_wait<0>();
        }
        __syncthreads();

        const float* tA = sA + buf * SA_BUF;
        const float* tB = sB + buf * SB_BUF;
#pragma unroll
        for (int kk = 0; kk < BK; kk += 8) {
            wmma::fragment<wmma::matrix_a, 16, 16, 8, wmma::precision::tf32, wmma::row_major> af[4];
            wmma::fragment<wmma::matrix_b, 16, 16, 8, wmma::precision::tf32, wmma::row_major> bf[4];
#pragma unroll
            for (int i = 0; i < 4; i++)
                wmma::load_matrix_sync(af[i], tA + (wm * 64 + i * 16) * SA_LD + kk, SA_LD);
#pragma unroll
            for (int j = 0; j < 4; j++)
                wmma::load_matrix_sync(bf[j], tB + kk * SB_LD + wn * 64 + j * 16, SB_LD);
#pragma unroll
            for (int i = 0; i < 4; i++)
#pragma unroll
                for (int j = 0; j < 4; j++)
                    wmma::mma_sync(acc[i][j], af[i], bf[j], acc[i][j]);
        }
        __syncthreads();
    }

#pragma unroll
    for (int i = 0; i < 4; i++)
#pragma unroll
        for (int j = 0; j < 4; j++) {
            float* cp = C + (size_t)(m0 + wm * 64 + i * 16) * N + n0 + wn * 64 + j * 16;
            wmma::store_matrix_sync(cp, acc[i][j], N, wmma::mem_row_major);
        }
}

// ======================================================================
// Fused RMSNorm + RoPE + tf32 rounding. One warp per (token, head).
// heads 0-31 q, 32-39 k (norm+rope), 40-47 v (round only).
// ======================================================================
__global__ __launch_bounds__(128) void normrope_kernel(float* __restrict__ qkv,
                                                       const int* __restrict__ positions,
                                                       const float* __restrict__ qw,
                                                       const float* __restrict__ kw)
{
    const int gw   = blockIdx.x * 4 + (threadIdx.x >> 5);
    const int lane = threadIdx.x & 31;
    const int total = T_TOK * 48;
    if (gw >= total) return;
    const int t  = gw / 48;
    const int hh = gw - t * 48;

    float* x = qkv + (size_t)t * QKV_N + hh * HD;
    float x0 = x[lane];
    float x1 = x[lane + 32];
    float x2 = x[lane + 64];
    float x3 = x[lane + 96];

    if (hh >= 40) {   // v head: just round to tf32
        x[lane]      = to_tf32(x0);
        x[lane + 32] = to_tf32(x1);
        x[lane + 64] = to_tf32(x2);
        x[lane + 96] = to_tf32(x3);
        return;
    }

    const float* w = (hh < NQ) ? qw : kw;

    float ss = x0 * x0 + x1 * x1 + x2 * x2 + x3 * x3;
#pragma unroll
    for (int o = 16; o; o >>= 1) ss += __shfl_xor_sync(0xffffffffu, ss, o);
    const float rinv = rsqrtf(ss * (1.0f / 128.0f) + 1e-6f);

    x0 *= rinv * w[lane];
    x1 *= rinv * w[lane + 32];
    x2 *= rinv * w[lane + 64];
    x3 *= rinv * w[lane + 96];

    const float p = (float)positions[t];
    const float inv0 = powf(1.0e6f, -((float)lane)        * (1.0f / 64.0f));
    const float inv1 = powf(1.0e6f, -((float)(lane + 32)) * (1.0f / 64.0f));
    float s0, c0, s1, c1;
    sincosf(p * inv0, &s0, &c0);
    sincosf(p * inv1, &s1, &c1);

    x[lane]      = to_tf32(x0 * c0 - x2 * s0);
    x[lane + 64] = to_tf32(x2 * c0 + x0 * s0);
    x[lane + 32] = to_tf32(x1 * c1 - x3 * s1);
    x[lane + 96] = to_tf32(x3 * c1 + x1 * s1);
}

// ======================================================================
// Flash attention v2-style, raw mma.sync tf32, O accumulators in registers.
// CTA = (128 q-rows, 1 head), 256 threads (8 warps), warp = 16 q-rows.
// Key tile = 64. P staged in per-warp-private smem.  (unchanged from R8)
// ======================================================================
#define ATQ 128
#define ATK 64
#define QLD 132
#define KLD 132
#define VLD 136
#define PLD 68
#define OFF_Q 0
#define OFF_K (ATQ * QLD)
#define OFF_V (OFF_K + ATK * KLD)
#define OFF_P (OFF_V + ATK * VLD)
#define ATTN_SMEM_FLOATS (OFF_P + 8 * 16 * PLD)
#define ATTN_SMEM_BYTES  (ATTN_SMEM_FLOATS * 4)   // 171008

__global__ __launch_bounds__(256, 1) void attn2_kernel(const float* __restrict__ qkv,
                                                       float* __restrict__ aout)
{
    extern __shared__ float sm[];
    const int tid  = threadIdx.x;
    const int lane = tid & 31;
    const int w    = tid >> 5;
    const int lq   = lane >> 2;
    const int lk   = lane & 3;

    const int qt  = gridDim.x - 1 - blockIdx.x;
    const int h   = blockIdx.y;
    const int kvh = h >> 2;
    const int q0  = qt * ATQ;
    const float scaling = 0.08838834764831845f;

    float* sQ = sm + OFF_Q;
    float* sK = sm + OFF_K;
    float* sV = sm + OFF_V;
    float* sP = sm + OFF_P + w * (16 * PLD);

#pragma unroll
    for (int i = 0; i < 16; i++) {
        int e = tid + i * 256;
        int r = e >> 5;
        int c = (e & 31) << 2;
        cp_async16(sQ + r * QLD + c, qkv + (size_t)(q0 + r) * QKV_N + h * HD + c);
    }
    cp_commit();

    float o[16][4];
#pragma unroll
    for (int t = 0; t < 16; t++) { o[t][0] = o[t][1] = o[t][2] = o[t][3] = 0.0f; }
    float m0 = -1e30f, m1 = -1e30f, l0 = 0.0f, l1 = 0.0f;

    const int grow0 = q0 + w * 16 + lq;
    const int nkt = 2 * (qt + 1);

    for (int kt = 0; kt < nkt; kt++) {
        const int k0 = kt * ATK;
        const float* kbase = qkv + (size_t)k0 * QKV_N + NQ * HD + kvh * HD;
        const float* vbase = kbase + NKV * HD;
#pragma unroll
        for (int i = 0; i < 8; i++) {
            int e = tid + i * 256;
            int r = e >> 5;
            int c = (e & 31) << 2;
            cp_async16(sK + r * KLD + c, kbase + (size_t)r * QKV_N + c);
        }
        cp_commit();
#pragma unroll
        for (int i = 0; i < 8; i++) {
            int e = tid + i * 256;
            int r = e >> 5;
            int c = (e & 31) << 2;
            cp_async16(sV + r * VLD + c, vbase + (size_t)r * QKV_N + c);
        }
        cp_commit();

        cp_wait<1>();
        __syncthreads();

        float s[8][4];
#pragma unroll
        for (int j = 0; j < 8; j++) { s[j][0] = s[j][1] = s[j][2] = s[j][3] = 0.0f; }

        {
            const float* qa = sQ + (w * 16 + lq) * QLD + lk;
            const float* kb = sK + lq * KLD + lk;
#pragma unroll
            for (int kk = 0; kk < 16; kk++) {
                const float a0 = qa[kk * 8];
                const float a1 = qa[8 * QLD + kk * 8];
                const float a2 = qa[kk * 8 + 4];
                const float a3 = qa[8 * QLD + kk * 8 + 4];
#pragma unroll
                for (int j = 0; j < 8; j++) {
                    const float b0 = kb[j * 8 * KLD + kk * 8];
                    const float b1 = kb[j * 8 * KLD + kk * 8 + 4];
                    mma_tf32_16x8x8(s[j][0], s[j][1], s[j][2], s[j][3],
                                    a0, a1, a2, a3, b0, b1);
                }
            }
        }

        const bool needmask = (k0 + ATK - 1 > grow0);
#pragma unroll
        for (int j = 0; j < 8; j++) {
            s[j][0] *= scaling; s[j][1] *= scaling;
            s[j][2] *= scaling; s[j][3] *= scaling;
            if (needmask) {
                const int c0 = k0 + j * 8 + 2 * lk;
                if (c0     > grow0)     s[j][0] = -1e30f;
                if (c0 + 1 > grow0)     s[j][1] = -1e30f;
                if (c0     > grow0 + 8) s[j][2] = -1e30f;
                if (c0 + 1 > grow0 + 8) s[j][3] = -1e30f;
            }
        }

        float rmax0 = -1e30f, rmax1 = -1e30f;
#pragma unroll
        for (int j = 0; j < 8; j++) {
            rmax0 = fmaxf(rmax0, fmaxf(s[j][0], s[j][1]));
            rmax1 = fmaxf(rmax1, fmaxf(s[j][2], s[j][3]));
        }
        rmax0 = fmaxf(rmax0, __shfl_xor_sync(0xffffffffu, rmax0, 1));
        rmax0 = fmaxf(rmax0, __shfl_xor_sync(0xffffffffu, rmax0, 2));
        rmax1 = fmaxf(rmax1, __shfl_xor_sync(0xffffffffu, rmax1, 1));
        rmax1 = fmaxf(rmax1, __shfl_xor_sync(0xffffffffu, rmax1, 2));

        const float mn0 = fmaxf(m0, rmax0);
        const float mn1 = fmaxf(m1, rmax1);
        const float alpha0 = __expf(m0 - mn0);
        const float alpha1 = __expf(m1 - mn1);
        m0 = mn0; m1 = mn1;

        float sum0 = 0.0f, sum1 = 0.0f;
#pragma unroll
        for (int j = 0; j < 8; j++) {
            const float p0 = __expf(s[j][0] - mn0);
            const float p1 = __expf(s[j][1] - mn0);
            const float p2 = __expf(s[j][2] - mn1);
            const float p3 = __expf(s[j][3] - mn1);
            sum0 += p0 + p1; sum1 += p2 + p3;
            float2* dst0 = (float2*)(sP + lq * PLD + j * 8 + 2 * lk);
            float2* dst1 = (float2*)(sP + (lq + 8) * PLD + j * 8 + 2 * lk);
            *dst0 = make_float2(p0, p1);
            *dst1 = make_float2(p2, p3);
        }
        sum0 += __shfl_xor_sync(0xffffffffu, sum0, 1);
        sum0 += __shfl_xor_sync(0xffffffffu, sum0, 2);
        sum1 += __shfl_xor_sync(0xffffffffu, sum1, 1);
        sum1 += __shfl_xor_sync(0xffffffffu, sum1, 2);
        l0 = l0 * alpha0 + sum0;
        l1 = l1 * alpha1 + sum1;

#pragma unroll
        for (int t = 0; t < 16; t++) {
            o[t][0] *= alpha0; o[t][1] *= alpha0;
            o[t][2] *= alpha1; o[t][3] *= alpha1;
        }

        cp_wait<0>();
        __syncthreads();

        {
            const float* pa = sP + lq * PLD + lk;
            const float* vb = sV + lk * VLD + lq;
#pragma unroll
            for (int kk = 0; kk < 8; kk++) {
                const float a0 = pa[kk * 8];
                const float a1 = pa[8 * PLD + kk * 8];
                const float a2 = pa[kk * 8 + 4];
                const float a3 = pa[8 * PLD + kk * 8 + 4];
#pragma unroll
                for (int t = 0; t < 16; t++) {
                    const float b0 = vb[kk * 8 * VLD + t * 8];
                    const float b1 = vb[(kk * 8 + 4) * VLD + t * 8];
                    mma_tf32_16x8x8(o[t][0], o[t][1], o[t][2], o[t][3],
                                    a0, a1, a2, a3, b0, b1);
                }
            }
        }
        __syncthreads();
    }

    const float inv0 = 1.0f / l0;
    const float inv1 = 1.0f / l1;
    const int row0 = q0 + w * 16 + lq;
#pragma unroll
    for (int t = 0; t < 16; t++) {
        const int c = t * 8 + 2 * lk;
        float2 v0 = make_float2(to_tf32(o[t][0] * inv0), to_tf32(o[t][1] * inv0));
        float2 v1 = make_float2(to_tf32(o[t][2] * inv1), to_tf32(o[t][3] * inv1));
        *(float2*)(aout + (size_t)row0 * O_N + h * HD + c)       = v0;
        *(float2*)(aout + (size_t)(row0 + 8) * O_N + h * HD + c) = v1;
    }
}

// ======================================================================
// Launch
// ======================================================================
extern "C" void kernel_launch(void* const* d_in, const int* in_sizes, int n_in,
                              void* d_out, int out_size)
{
    (void)in_sizes; (void)n_in; (void)out_size;
    const int*   positions = (const int*)  d_in[0];
    const float* hidden    = (const float*)d_in[1];
    const float* w_qkv     = (const float*)d_in[2];
    const float* qw        = (const float*)d_in[3];
    const float* kw        = (const float*)d_in[4];
    const float* w_o       = (const float*)d_in[5];
    float*       out       = (float*)d_out;

    float *qkv_ptr, *attn_ptr, *hid_r, *wqkv_r, *wo_r;
    cudaGetSymbolAddress((void**)&qkv_ptr, g_qkv);
    cudaGetSymbolAddress((void**)&attn_ptr, g_attn);
    cudaGetSymbolAddress((void**)&hid_r,  g_hid_r);
    cudaGetSymbolAddress((void**)&wqkv_r, g_wqkv_r);
    cudaGetSymbolAddress((void**)&wo_r,   g_wo_r);

    cudaFuncSetAttribute(gemm_tf32,  cudaFuncAttributeMaxDynamicSharedMemorySize, GEMM_SMEM_BYTES);
    cudaFuncSetAttribute(attn2_kernel, cudaFuncAttributeMaxDynamicSharedMemorySize, ATTN_SMEM_BYTES);

    // 0) pre-round GEMM operands to tf32 (RNA, once)
    {
        int n4;
        n4 = (T_TOK * HID) / 4;
        round_tf32_kernel<<<(n4 + 255) / 256, 256>>>((const float4*)hidden, (float4*)hid_r, n4);
        n4 = (HID * QKV_N) / 4;
        round_tf32_kernel<<<(n4 + 255) / 256, 256>>>((const float4*)w_qkv, (float4*)wqkv_r, n4);
        n4 = (HID * O_N) / 4;
        round_tf32_kernel<<<(n4 + 255) / 256, 256>>>((const float4*)w_o, (float4*)wo_r, n4);
    }

    // 1) qkv = hidden @ w_qkv
    gemm_tf32<<<dim3(QKV_N / BN, T_TOK / BM), 256, GEMM_SMEM_BYTES>>>(hid_r, wqkv_r, qkv_ptr, T_TOK, QKV_N, HID);
    // 2) rmsnorm + rope + tf32 rounding, in place
    normrope_kernel<<<(T_TOK * 48) / 4, 128>>>(qkv_ptr, positions, qw, kw);
    // 3) causal flash attention (register-resident O)
    attn2_kernel<<<dim3(T_TOK / ATQ, NQ), 256, ATTN_SMEM_BYTES>>>(qkv_ptr, attn_ptr);
    // 4) out = attn @ w_o
    gemm_tf32<<<dim3(O_N / BN, T_TOK / BM), 256, GEMM_SMEM_BYTES>>>(attn_ptr, wo_r, out, T_TOK, O_N, HID);
}

// round 15
// speedup vs baseline: 1.6823x; 1.0481x over previous
#include <cuda_runtime.h>
#include <mma.h>

using namespace nvcuda;

// ---------------- Problem constants ----------------
#define T_TOK   2048
#define HID     4096
#define NQ      32
#define NKV     8
#define HD      128
#define QKV_N   6144            // (32 + 2*8) * 128
#define O_N     4096            // NQ * HD

// Scratch (allocation-free rule: __device__ globals)
__device__ float g_qkv [(size_t)T_TOK * QKV_N];
__device__ float g_attn[(size_t)T_TOK * O_N];
__device__ float g_hid_r [(size_t)T_TOK * HID];
__device__ float g_wqkv_r[(size_t)HID * QKV_N];
__device__ float g_wo_r  [(size_t)HID * O_N];

__device__ __forceinline__ float to_tf32(float x) {
    float r;
    asm("cvt.rna.tf32.f32 %0, %1;" : "=f"(r) : "f"(x));
    return r;
}

// ---------------- cp.async helpers ----------------
__device__ __forceinline__ void cp_async16(void* smem_dst, const void* gmem_src) {
    unsigned s = (unsigned)__cvta_generic_to_shared(smem_dst);
    asm volatile("cp.async.cg.shared.global [%0], [%1], 16;\n" :: "r"(s), "l"(gmem_src));
}
__device__ __forceinline__ void cp_commit() {
    asm volatile("cp.async.commit_group;\n");
}
template <int N>
__device__ __forceinline__ void cp_wait() {
    asm volatile("cp.async.wait_group %0;\n" :: "n"(N));
}

// ---------------- raw tf32 mma (m16n8k8) for attention ----------------
__device__ __forceinline__ void mma_tf32_16x8x8(float& d0, float& d1, float& d2, float& d3,
                                                float a0, float a1, float a2, float a3,
                                                float b0, float b1)
{
    asm volatile(
        "mma.sync.aligned.m16n8k8.row.col.f32.tf32.tf32.f32 "
        "{%0,%1,%2,%3}, {%4,%5,%6,%7}, {%8,%9}, {%0,%1,%2,%3};\n"
        : "+f"(d0), "+f"(d1), "+f"(d2), "+f"(d3)
        : "r"(__float_as_uint(a0)), "r"(__float_as_uint(a1)),
          "r"(__float_as_uint(a2)), "r"(__float_as_uint(a3)),
          "r"(__float_as_uint(b0)), "r"(__float_as_uint(b1)));
}

// ======================================================================
// Elementwise RNA-round to tf32 (float4 vectorized)
// ======================================================================
__global__ __launch_bounds__(256) void round_tf32_kernel(const float4* __restrict__ in,
                                                         float4* __restrict__ out, int n4)
{
    int i = blockIdx.x * 256 + threadIdx.x;
    if (i < n4) {
        float4 v = in[i];
        v.x = to_tf32(v.x); v.y = to_tf32(v.y);
        v.z = to_tf32(v.z); v.w = to_tf32(v.w);
        out[i] = v;
    }
}

// ======================================================================
// TF32 wmma GEMM: C[M,N] = A[M,K] @ B[K,N], row-major, inputs pre-rounded.
// Block tile 128x128x32, 128 threads (4 warps), warp tile 64x64.
// 2-stage cp.async double buffer, 2 CTAs/SM (two independent barrier
// domains keep the tensor pipe fed across syncs). Per kk step per warp:
// 8 fragment loads + 16 wmma (0.5 LDS-instr/MMA, 16 indep acc chains).
// ======================================================================
#define BM 128
#define BN 128
#define BK 32
#define SA_LD 40     // 32 + 8 pad
#define SB_LD 136    // 128 + 8 pad
#define SA_BUF (BM * SA_LD)          // 5120 floats
#define SB_BUF (BK * SB_LD)          // 4352 floats
#define GEMM_SMEM_BYTES (2 * (SA_BUF + SB_BUF) * 4)   // 75776 B

__global__ __launch_bounds__(128, 2) void gemm_tf32(const float* __restrict__ A,
                                                    const float* __restrict__ B,
                                                    float* __restrict__ C,
                                                    int M, int N, int K)
{
    extern __shared__ float smem[];
    float* sA = smem;                     // 2 buffers
    float* sB = smem + 2 * SA_BUF;        // 2 buffers

    const int tid  = threadIdx.x;
    const int warp = tid >> 5;
    const int wm   = warp >> 1;       // 0..1  (64-row band)
    const int wn   = warp & 1;        // 0..1  (64-col band)
    const int m0   = blockIdx.y * BM;
    const int n0   = blockIdx.x * BN;

    // A tile 128x32 = 1024 float4 -> 8 per thread; B tile 32x128 = 1024 -> 8
    const int ca = (tid & 7) << 2;
    const int cb = (tid & 31) << 2;

    wmma::fragment<wmma::accumulator, 16, 16, 8, float> acc[4][4];
#pragma unroll
    for (int i = 0; i < 4; i++)
#pragma unroll
        for (int j = 0; j < 4; j++)
            wmma::fill_fragment(acc[i][j], 0.0f);

    const int NT = K / BK;

    auto load_tile = [&](int kt, int buf) {
        const int kb = kt * BK;
        float* dA = sA + buf * SA_BUF;
        float* dB = sB + buf * SB_BUF;
#pragma unroll
        for (int i = 0; i < 8; i++) {
            int r = (tid + i * 128) >> 3;
            cp_async16(dA + r * SA_LD + ca, A + (size_t)(m0 + r) * K + kb + ca);
        }
#pragma unroll
        for (int i = 0; i < 8; i++) {
            int r = (tid + i * 128) >> 5;
            cp_async16(dB + r * SB_LD + cb, B + (size_t)(kb + r) * N + n0 + cb);
        }
    };

    load_tile(0, 0);
    cp_commit();

    for (int kt = 0; kt < NT; kt++) {
        const int buf = kt & 1;
        if (kt + 1 < NT) {
            load_tile(kt + 1, (kt + 1) & 1);
            cp_commit();
            cp_wait<1>();
        } else {
            cp_wait<0>();
        }
        __syncthreads();

        const float* tA = sA + buf * SA_BUF;
        const float* tB = sB + buf * SB_BUF;
#pragma unroll
        for (int kk = 0; kk < BK; kk += 8) {
            wmma::fragment<wmma::matrix_a, 16, 16, 8, wmma::precision::tf32, wmma::row_major> af[4];
            wmma::fragment<wmma::matrix_b, 16, 16, 8, wmma::precision::tf32, wmma::row_major> bf[4];
#pragma unroll
            for (int i = 0; i < 4; i++)
                wmma::load_matrix_sync(af[i], tA + (wm * 64 + i * 16) * SA_LD + kk, SA_LD);
#pragma unroll
            for (int j = 0; j < 4; j++)
                wmma::load_matrix_sync(bf[j], tB + kk * SB_LD + wn * 64 + j * 16, SB_LD);
#pragma unroll
            for (int i = 0; i < 4; i++)
#pragma unroll
                for (int j = 0; j < 4; j++)
                    wmma::mma_sync(acc[i][j], af[i], bf[j], acc[i][j]);
        }
        __syncthreads();
    }

#pragma unroll
    for (int i = 0; i < 4; i++)
#pragma unroll
        for (int j = 0; j < 4; j++) {
            float* cp = C + (size_t)(m0 + wm * 64 + i * 16) * N + n0 + wn * 64 + j * 16;
            wmma::store_matrix_sync(cp, acc[i][j], N, wmma::mem_row_major);
        }
}

// ======================================================================
// Fused RMSNorm + RoPE + tf32 rounding. One warp per (token, head).
// heads 0-31 q, 32-39 k (norm+rope), 40-47 v (round only).
// ======================================================================
__global__ __launch_bounds__(128) void normrope_kernel(float* __restrict__ qkv,
                                                       const int* __restrict__ positions,
                                                       const float* __restrict__ qw,
                                                       const float* __restrict__ kw)
{
    const int gw   = blockIdx.x * 4 + (threadIdx.x >> 5);
    const int lane = threadIdx.x & 31;
    const int total = T_TOK * 48;
    if (gw >= total) return;
    const int t  = gw / 48;
    const int hh = gw - t * 48;

    float* x = qkv + (size_t)t * QKV_N + hh * HD;
    float x0 = x[lane];
    float x1 = x[lane + 32];
    float x2 = x[lane + 64];
    float x3 = x[lane + 96];

    if (hh >= 40) {   // v head: just round to tf32
        x[lane]      = to_tf32(x0);
        x[lane + 32] = to_tf32(x1);
        x[lane + 64] = to_tf32(x2);
        x[lane + 96] = to_tf32(x3);
        return;
    }

    const float* w = (hh < NQ) ? qw : kw;

    float ss = x0 * x0 + x1 * x1 + x2 * x2 + x3 * x3;
#pragma unroll
    for (int o = 16; o; o >>= 1) ss += __shfl_xor_sync(0xffffffffu, ss, o);
    const float rinv = rsqrtf(ss * (1.0f / 128.0f) + 1e-6f);

    x0 *= rinv * w[lane];
    x1 *= rinv * w[lane + 32];
    x2 *= rinv * w[lane + 64];
    x3 *= rinv * w[lane + 96];

    const float p = (float)positions[t];
    const float inv0 = powf(1.0e6f, -((float)lane)        * (1.0f / 64.0f));
    const float inv1 = powf(1.0e6f, -((float)(lane + 32)) * (1.0f / 64.0f));
    float s0, c0, s1, c1;
    sincosf(p * inv0, &s0, &c0);
    sincosf(p * inv1, &s1, &c1);

    x[lane]      = to_tf32(x0 * c0 - x2 * s0);
    x[lane + 64] = to_tf32(x2 * c0 + x0 * s0);
    x[lane + 32] = to_tf32(x1 * c1 - x3 * s1);
    x[lane + 96] = to_tf32(x3 * c1 + x1 * s1);
}

// ======================================================================
// Flash attention v2-style, raw mma.sync tf32, O accumulators in registers.
// CTA = (128 q-rows, 1 head), 256 threads (8 warps), warp = 16 q-rows.
// Key tile = 64. P staged in per-warp-private smem.  (unchanged from R8)
// ======================================================================
#define ATQ 128
#define ATK 64
#define QLD 132
#define KLD 132
#define VLD 136
#define PLD 68
#define OFF_Q 0
#define OFF_K (ATQ * QLD)
#define OFF_V (OFF_K + ATK * KLD)
#define OFF_P (OFF_V + ATK * VLD)
#define ATTN_SMEM_FLOATS (OFF_P + 8 * 16 * PLD)
#define ATTN_SMEM_BYTES  (ATTN_SMEM_FLOATS * 4)   // 171008

__global__ __launch_bounds__(256, 1) void attn2_kernel(const float* __restrict__ qkv,
                                                       float* __restrict__ aout)
{
    extern __shared__ float sm[];
    const int tid  = threadIdx.x;
    const int lane = tid & 31;
    const int w    = tid >> 5;
    const int lq   = lane >> 2;
    const int lk   = lane & 3;

    const int qt  = gridDim.x - 1 - blockIdx.x;
    const int h   = blockIdx.y;
    const int kvh = h >> 2;
    const int q0  = qt * ATQ;
    const float scaling = 0.08838834764831845f;

    float* sQ = sm + OFF_Q;
    float* sK = sm + OFF_K;
    float* sV = sm + OFF_V;
    float* sP = sm + OFF_P + w * (16 * PLD);

#pragma unroll
    for (int i = 0; i < 16; i++) {
        int e = tid + i * 256;
        int r = e >> 5;
        int c = (e & 31) << 2;
        cp_async16(sQ + r * QLD + c, qkv + (size_t)(q0 + r) * QKV_N + h * HD + c);
    }
    cp_commit();

    float o[16][4];
#pragma unroll
    for (int t = 0; t < 16; t++) { o[t][0] = o[t][1] = o[t][2] = o[t][3] = 0.0f; }
    float m0 = -1e30f, m1 = -1e30f, l0 = 0.0f, l1 = 0.0f;

    const int grow0 = q0 + w * 16 + lq;
    const int nkt = 2 * (qt + 1);

    for (int kt = 0; kt < nkt; kt++) {
        const int k0 = kt * ATK;
        const float* kbase = qkv + (size_t)k0 * QKV_N + NQ * HD + kvh * HD;
        const float* vbase = kbase + NKV * HD;
#pragma unroll
        for (int i = 0; i < 8; i++) {
            int e = tid + i * 256;
            int r = e >> 5;
            int c = (e & 31) << 2;
            cp_async16(sK + r * KLD + c, kbase + (size_t)r * QKV_N + c);
        }
        cp_commit();
#pragma unroll
        for (int i = 0; i < 8; i++) {
            int e = tid + i * 256;
            int r = e >> 5;
            int c = (e & 31) << 2;
            cp_async16(sV + r * VLD + c, vbase + (size_t)r * QKV_N + c);
        }
        cp_commit();

        cp_wait<1>();
        __syncthreads();

        float s[8][4];
#pragma unroll
        for (int j = 0; j < 8; j++) { s[j][0] = s[j][1] = s[j][2] = s[j][3] = 0.0f; }

        {
            const float* qa = sQ + (w * 16 + lq) * QLD + lk;
            const float* kb = sK + lq * KLD + lk;
#pragma unroll
            for (int kk = 0; kk < 16; kk++) {
                const float a0 = qa[kk * 8];
                const float a1 = qa[8 * QLD + kk * 8];
                const float a2 = qa[kk * 8 + 4];
                const float a3 = qa[8 * QLD + kk * 8 + 4];
#pragma unroll
                for (int j = 0; j < 8; j++) {
                    const float b0 = kb[j * 8 * KLD + kk * 8];
                    const float b1 = kb[j * 8 * KLD + kk * 8 + 4];
                    mma_tf32_16x8x8(s[j][0], s[j][1], s[j][2], s[j][3],
                                    a0, a1, a2, a3, b0, b1);
                }
            }
        }

        const bool needmask = (k0 + ATK - 1 > grow0);
#pragma unroll
        for (int j = 0; j < 8; j++) {
            s[j][0] *= scaling; s[j][1] *= scaling;
            s[j][2] *= scaling; s[j][3] *= scaling;
            if (needmask) {
                const int c0 = k0 + j * 8 + 2 * lk;
                if (c0     > grow0)     s[j][0] = -1e30f;
                if (c0 + 1 > grow0)     s[j][1] = -1e30f;
                if (c0     > grow0 + 8) s[j][2] = -1e30f;
                if (c0 + 1 > grow0 + 8) s[j][3] = -1e30f;
            }
        }

        float rmax0 = -1e30f, rmax1 = -1e30f;
#pragma unroll
        for (int j = 0; j < 8; j++) {
            rmax0 = fmaxf(rmax0, fmaxf(s[j][0], s[j][1]));
            rmax1 = fmaxf(rmax1, fmaxf(s[j][2], s[j][3]));
        }
        rmax0 = fmaxf(rmax0, __shfl_xor_sync(0xffffffffu, rmax0, 1));
        rmax0 = fmaxf(rmax0, __shfl_xor_sync(0xffffffffu, rmax0, 2));
        rmax1 = fmaxf(rmax1, __shfl_xor_sync(0xffffffffu, rmax1, 1));
        rmax1 = fmaxf(rmax1, __shfl_xor_sync(0xffffffffu, rmax1, 2));

        const float mn0 = fmaxf(m0, rmax0);
        const float mn1 = fmaxf(m1, rmax1);
        const float alpha0 = __expf(m0 - mn0);
        const float alpha1 = __expf(m1 - mn1);
        m0 = mn0; m1 = mn1;

        float sum0 = 0.0f, sum1 = 0.0f;
#pragma unroll
        for (int j = 0; j < 8; j++) {
            const float p0 = __expf(s[j][0] - mn0);
            const float p1 = __expf(s[j][1] - mn0);
            const float p2 = __expf(s[j][2] - mn1);
            const float p3 = __expf(s[j][3] - mn1);
            sum0 += p0 + p1; sum1 += p2 + p3;
            float2* dst0 = (float2*)(sP + lq * PLD + j * 8 + 2 * lk);
            float2* dst1 = (float2*)(sP + (lq + 8) * PLD + j * 8 + 2 * lk);
            *dst0 = make_float2(p0, p1);
            *dst1 = make_float2(p2, p3);
        }
        sum0 += __shfl_xor_sync(0xffffffffu, sum0, 1);
        sum0 += __shfl_xor_sync(0xffffffffu, sum0, 2);
        sum1 += __shfl_xor_sync(0xffffffffu, sum1, 1);
        sum1 += __shfl_xor_sync(0xffffffffu, sum1, 2);
        l0 = l0 * alpha0 + sum0;
        l1 = l1 * alpha1 + sum1;

#pragma unroll
        for (int t = 0; t < 16; t++) {
            o[t][0] *= alpha0; o[t][1] *= alpha0;
            o[t][2] *= alpha1; o[t][3] *= alpha1;
        }

        cp_wait<0>();
        __syncthreads();

        {
            const float* pa = sP + lq * PLD + lk;
            const float* vb = sV + lk * VLD + lq;
#pragma unroll
            for (int kk = 0; kk < 8; kk++) {
                const float a0 = pa[kk * 8];
                const float a1 = pa[8 * PLD + kk * 8];
                const float a2 = pa[kk * 8 + 4];
                const float a3 = pa[8 * PLD + kk * 8 + 4];
#pragma unroll
                for (int t = 0; t < 16; t++) {
                    const float b0 = vb[kk * 8 * VLD + t * 8];
                    const float b1 = vb[(kk * 8 + 4) * VLD + t * 8];
                    mma_tf32_16x8x8(o[t][0], o[t][1], o[t][2], o[t][3],
                                    a0, a1, a2, a3, b0, b1);
                }
            }
        }
        __syncthreads();
    }

    const float inv0 = 1.0f / l0;
    const float inv1 = 1.0f / l1;
    const int row0 = q0 + w * 16 + lq;
#pragma unroll
    for (int t = 0; t < 16; t++) {
        const int c = t * 8 + 2 * lk;
        float2 v0 = make_float2(to_tf32(o[t][0] * inv0), to_tf32(o[t][1] * inv0));
        float2 v1 = make_float2(to_tf32(o[t][2] * inv1), to_tf32(o[t][3] * inv1));
        *(float2*)(aout + (size_t)row0 * O_N + h * HD + c)       = v0;
        *(float2*)(aout + (size_t)(row0 + 8) * O_N + h * HD + c) = v1;
    }
}

// ======================================================================
// Launch
// ======================================================================
extern "C" void kernel_launch(void* const* d_in, const int* in_sizes, int n_in,
                              void* d_out, int out_size)
{
    (void)in_sizes; (void)n_in; (void)out_size;
    const int*   positions = (const int*)  d_in[0];
    const float* hidden    = (const float*)d_in[1];
    const float* w_qkv     = (const float*)d_in[2];
    const float* qw        = (const float*)d_in[3];
    const float* kw        = (const float*)d_in[4];
    const float* w_o       = (const float*)d_in[5];
    float*       out       = (float*)d_out;

    float *qkv_ptr, *attn_ptr, *hid_r, *wqkv_r, *wo_r;
    cudaGetSymbolAddress((void**)&qkv_ptr, g_qkv);
    cudaGetSymbolAddress((void**)&attn_ptr, g_attn);
    cudaGetSymbolAddress((void**)&hid_r,  g_hid_r);
    cudaGetSymbolAddress((void**)&wqkv_r, g_wqkv_r);
    cudaGetSymbolAddress((void**)&wo_r,   g_wo_r);

    cudaFuncSetAttribute(gemm_tf32,  cudaFuncAttributeMaxDynamicSharedMemorySize, GEMM_SMEM_BYTES);
    cudaFuncSetAttribute(attn2_kernel, cudaFuncAttributeMaxDynamicSharedMemorySize, ATTN_SMEM_BYTES);

    // 0) pre-round GEMM operands to tf32 (RNA, once)
    {
        int n4;
        n4 = (T_TOK * HID) / 4;
        round_tf32_kernel<<<(n4 + 255) / 256, 256>>>((const float4*)hidden, (float4*)hid_r, n4);
        n4 = (HID * QKV_N) / 4;
        round_tf32_kernel<<<(n4 + 255) / 256, 256>>>((const float4*)w_qkv, (float4*)wqkv_r, n4);
        n4 = (HID * O_N) / 4;
        round_tf32_kernel<<<(n4 + 255) / 256, 256>>>((const float4*)w_o, (float4*)wo_r, n4);
    }

    // 1) qkv = hidden @ w_qkv
    gemm_tf32<<<dim3(QKV_N / BN, T_TOK / BM), 128, GEMM_SMEM_BYTES>>>(hid_r, wqkv_r, qkv_ptr, T_TOK, QKV_N, HID);
    // 2) rmsnorm + rope + tf32 rounding, in place
    normrope_kernel<<<(T_TOK * 48) / 4, 128>>>(qkv_ptr, positions, qw, kw);
    // 3) causal flash attention (register-resident O)
    attn2_kernel<<<dim3(T_TOK / ATQ, NQ), 256, ATTN_SMEM_BYTES>>>(qkv_ptr, attn_ptr);
    // 4) out = attn @ w_o
    gemm_tf32<<<dim3(O_N / BN, T_TOK / BM), 128, GEMM_SMEM_BYTES>>>(attn_ptr, wo_r, out, T_TOK, O_N, HID);
}